// round 9
// baseline (speedup 1.0000x reference)
#include <cuda_runtime.h>
#include <cuda_bf16.h>
#include <cstdint>

#define BB 8
#define NN 2048
#define DD 256
#define K3 768            // 3-term split K' = 3*DD (bf16)
#define KK 100
#define RR 5
#define BIGV 1000000000.0f
#define LN_EPS 1e-5f

// GEMM tiling
#define BM 128
#define BN 128
#define BKE 64                         // bf16 elems per stage (128 B/row)
#define PADB 72                        // padded row stride in bf16 elems
#define STAGE_H (2 * BM * PADB)        // halves per stage (A+B) = 18432
#define SMEM_BYTES (2 * STAGE_H * 2)   // 73728

// ---- scratch (device globals; no allocations allowed) ----
__device__ __align__(128) __nv_bfloat16 g_qsb[(size_t)BB * NN * K3];
__device__ __align__(128) __nv_bfloat16 g_ksb[(size_t)BB * NN * K3];
__device__ float g_diag[BB * NN];
__device__ int   g_sel[BB * NN];
__device__ int   g_topidx[BB * KK];
__device__ int   g_pairs[BB * KK * RR * 2];

// ============================================================
// helpers
// ============================================================
__device__ __forceinline__ void ldsm4(unsigned& r0, unsigned& r1, unsigned& r2, unsigned& r3,
                                      unsigned addr) {
    asm volatile("ldmatrix.sync.aligned.m8n8.x4.shared.b16 {%0,%1,%2,%3}, [%4];"
                 : "=r"(r0), "=r"(r1), "=r"(r2), "=r"(r3) : "r"(addr));
}
__device__ __forceinline__ void mma_bf16(float* d, const unsigned* a, const unsigned* b) {
    asm volatile("mma.sync.aligned.m16n8k16.row.col.f32.bf16.bf16.f32 "
                 "{%0,%1,%2,%3},{%4,%5,%6,%7},{%8,%9},{%0,%1,%2,%3};"
                 : "+f"(d[0]), "+f"(d[1]), "+f"(d[2]), "+f"(d[3])
                 : "r"(a[0]), "r"(a[1]), "r"(a[2]), "r"(a[3]), "r"(b[0]), "r"(b[1]));
}
__device__ __forceinline__ void cpa16(void* smem_dst, const void* gsrc) {
    unsigned d = (unsigned)__cvta_generic_to_shared(smem_dst);
    asm volatile("cp.async.cg.shared.global [%0], [%1], 16;" :: "r"(d), "l"(gsrc));
}

// ============================================================
// Kernel 0: bf16 3-term split.  q -> [qh,qh,ql] ; k -> [kh,kl,kh]
// ============================================================
__global__ __launch_bounds__(256) void split3b_kernel(
    const float* __restrict__ q, const float* __restrict__ k)
{
    const bool isK = blockIdx.y != 0;
    const float4* src = (const float4*)(isK ? k : q);
    __nv_bfloat16* dst = isK ? g_ksb : g_qsb;
    size_t i = (size_t)blockIdx.x * 256 + threadIdx.x;

    float4 v0 = src[2 * i];
    float4 v1 = src[2 * i + 1];
    float xs[8] = {v0.x, v0.y, v0.z, v0.w, v1.x, v1.y, v1.z, v1.w};

    __align__(16) __nv_bfloat16 out[24];
#pragma unroll
    for (int e = 0; e < 8; e++) {
        __nv_bfloat16 h = __float2bfloat16(xs[e]);
        __nv_bfloat16 l = __float2bfloat16(xs[e] - __bfloat162float(h));
        if (!isK) { out[3 * e] = h; out[3 * e + 1] = h; out[3 * e + 2] = l; }
        else      { out[3 * e] = h; out[3 * e + 1] = l; out[3 * e + 2] = h; }
    }
    uint4* o = (uint4*)(dst + 24 * i);
    o[0] = ((uint4*)out)[0];
    o[1] = ((uint4*)out)[1];
    o[2] = ((uint4*)out)[2];
}

// ============================================================
// Kernel 1: bf16 mma.sync m16n8k16 GEMM over K'=768
// ============================================================
__global__ __launch_bounds__(256, 2) void gemm_bf16k(
    const __nv_bfloat16* __restrict__ A0, const __nv_bfloat16* __restrict__ B0,
    float* __restrict__ out)
{
    extern __shared__ __nv_bfloat16 sm[];
    const int b = blockIdx.z;
    const int row0 = blockIdx.y * BM;
    const int col0 = blockIdx.x * BN;
    const __nv_bfloat16* A  = A0 + (size_t)b * NN * K3;
    const __nv_bfloat16* Bm = B0 + (size_t)b * NN * K3;
    float* C = out + (size_t)b * NN * NN;

    const int tid = threadIdx.x;
    const int warp = tid >> 5, lane = tid & 31;
    const int wm = (warp >> 2) * 64;
    const int wn = (warp & 3) * 32;

    float acc[4][4][4];
#pragma unroll
    for (int mf = 0; mf < 4; mf++)
#pragma unroll
        for (int nf = 0; nf < 4; nf++)
#pragma unroll
            for (int e = 0; e < 4; e++) acc[mf][nf][e] = 0.0f;

#define LOAD_STAGE(s, kt)                                                      \
    do {                                                                       \
        __nv_bfloat16* As_ = sm + (s) * STAGE_H;                               \
        __nv_bfloat16* Bs_ = As_ + BM * PADB;                                  \
        _Pragma("unroll")                                                      \
        for (int l = 0; l < 4; l++) {                                          \
            int idx = tid + l * 256;                                           \
            int row = idx >> 3;                                                \
            int ce  = (idx & 7) * 8;                                           \
            cpa16(&As_[row * PADB + ce], &A [(size_t)(row0 + row) * K3 + (kt) + ce]); \
            cpa16(&Bs_[row * PADB + ce], &Bm[(size_t)(col0 + row) * K3 + (kt) + ce]); \
        }                                                                      \
        asm volatile("cp.async.commit_group;");                                \
    } while (0)

    LOAD_STAGE(0, 0);

    const int NT = K3 / BKE;   // 12
#pragma unroll 2
    for (int t = 0; t < NT; t++) {
        const int cur = t & 1;
        if (t + 1 < NT) {
            LOAD_STAGE(cur ^ 1, (t + 1) * BKE);
            asm volatile("cp.async.wait_group 1;");
        } else {
            asm volatile("cp.async.wait_group 0;");
        }
        __syncthreads();

        const __nv_bfloat16* As_ = sm + cur * STAGE_H;
        const __nv_bfloat16* Bs_ = As_ + BM * PADB;

#pragma unroll
        for (int kk = 0; kk < 4; kk++) {
            const int kb = kk * 16;

            unsigned a[4][4];
#pragma unroll
            for (int mf = 0; mf < 4; mf++) {
                int arow = wm + mf * 16 + (lane & 15);
                int acol = kb + ((lane >> 4) << 3);
                unsigned addr = (unsigned)__cvta_generic_to_shared(&As_[arow * PADB + acol]);
                ldsm4(a[mf][0], a[mf][1], a[mf][2], a[mf][3], addr);
            }
            unsigned bf[4][2];
#pragma unroll
            for (int half = 0; half < 2; half++) {
                int brow = wn + half * 16 + (lane & 7) + ((lane >> 4) << 3);
                int bcol = kb + (((lane >> 3) & 1) << 3);
                unsigned addr = (unsigned)__cvta_generic_to_shared(&Bs_[brow * PADB + bcol]);
                ldsm4(bf[half * 2][0], bf[half * 2][1],
                      bf[half * 2 + 1][0], bf[half * 2 + 1][1], addr);
            }
#pragma unroll
            for (int mf = 0; mf < 4; mf++)
#pragma unroll
                for (int nf = 0; nf < 4; nf++)
                    mma_bf16(acc[mf][nf], a[mf], bf[nf]);
        }
        __syncthreads();
    }
#undef LOAD_STAGE

#pragma unroll
    for (int mf = 0; mf < 4; mf++)
#pragma unroll
        for (int nf = 0; nf < 4; nf++) {
            int r0 = row0 + wm + mf * 16 + (lane >> 2);
            int c0 = col0 + wn + nf * 8 + (lane & 3) * 2;
            *(float2*)&C[(size_t)r0 * NN + c0] =
                make_float2(acc[mf][nf][0], acc[mf][nf][1]);
            *(float2*)&C[(size_t)(r0 + 8) * NN + c0] =
                make_float2(acc[mf][nf][2], acc[mf][nf][3]);
        }
}

// ============================================================
// Kernel 2: in-place row softmax; extract diag.
// 128 threads/row, FOUR float4 per thread (fat threads, MLP=4)
// ============================================================
__global__ __launch_bounds__(128) void softmax_kernel(float* __restrict__ scores)
{
    const int rowg = blockIdx.x;
    const int i    = rowg & (NN - 1);
    float* row = scores + (size_t)rowg * NN;
    const int t = threadIdx.x;

    float4 v0 = ((float4*)row)[t];
    float4 v1 = ((float4*)row)[t + 128];
    float4 v2 = ((float4*)row)[t + 256];
    float4 v3 = ((float4*)row)[t + 384];

    float m01 = fmaxf(fmaxf(fmaxf(v0.x, v0.y), fmaxf(v0.z, v0.w)),
                      fmaxf(fmaxf(v1.x, v1.y), fmaxf(v1.z, v1.w)));
    float m23 = fmaxf(fmaxf(fmaxf(v2.x, v2.y), fmaxf(v2.z, v2.w)),
                      fmaxf(fmaxf(v3.x, v3.y), fmaxf(v3.z, v3.w)));
    float m = fmaxf(m01, m23);

    __shared__ float red[4];
#pragma unroll
    for (int o = 16; o > 0; o >>= 1) m = fmaxf(m, __shfl_xor_sync(0xffffffffu, m, o));
    if ((t & 31) == 0) red[t >> 5] = m;
    __syncthreads();
    float bm = fmaxf(fmaxf(red[0], red[1]), fmaxf(red[2], red[3]));
    __syncthreads();

    v0.x = __expf(v0.x - bm); v0.y = __expf(v0.y - bm);
    v0.z = __expf(v0.z - bm); v0.w = __expf(v0.w - bm);
    v1.x = __expf(v1.x - bm); v1.y = __expf(v1.y - bm);
    v1.z = __expf(v1.z - bm); v1.w = __expf(v1.w - bm);
    v2.x = __expf(v2.x - bm); v2.y = __expf(v2.y - bm);
    v2.z = __expf(v2.z - bm); v2.w = __expf(v2.w - bm);
    v3.x = __expf(v3.x - bm); v3.y = __expf(v3.y - bm);
    v3.z = __expf(v3.z - bm); v3.w = __expf(v3.w - bm);

    float s = v0.x + v0.y + v0.z + v0.w + v1.x + v1.y + v1.z + v1.w
            + v2.x + v2.y + v2.z + v2.w + v3.x + v3.y + v3.z + v3.w;
#pragma unroll
    for (int o = 16; o > 0; o >>= 1) s += __shfl_xor_sync(0xffffffffu, s, o);
    if ((t & 31) == 0) red[t >> 5] = s;
    __syncthreads();
    float bs = red[0] + red[1] + red[2] + red[3];

    const float inv = 1.0f / bs;
    v0.x *= inv; v0.y *= inv; v0.z *= inv; v0.w *= inv;
    v1.x *= inv; v1.y *= inv; v1.z *= inv; v1.w *= inv;
    v2.x *= inv; v2.y *= inv; v2.z *= inv; v2.w *= inv;
    v3.x *= inv; v3.y *= inv; v3.z *= inv; v3.w *= inv;

    ((float4*)row)[t]       = v0;
    ((float4*)row)[t + 128] = v1;
    ((float4*)row)[t + 256] = v2;
    ((float4*)row)[t + 384] = v3;

    const int c4 = i >> 2;          // which float4 holds the diag
    if ((c4 & 127) == t) {
        const int slot = c4 >> 7;   // 0..3
        float4 vv = (slot == 0) ? v0 : (slot == 1) ? v1 : (slot == 2) ? v2 : v3;
        int cc = i & 3;
        float d = (cc == 0) ? vv.x : (cc == 1) ? vv.y : (cc == 2) ? vv.z : vv.w;
        g_diag[rowg] = d;
    }
}

// ============================================================
// Kernel 3a: rank counting — one WARP per element
// ============================================================
__global__ __launch_bounds__(256) void topk_count_kernel()
{
    const int b = blockIdx.y;
    __shared__ __align__(16) float v[NN];

    for (int i = threadIdx.x; i < NN / 4; i += 256)
        ((float4*)v)[i] = ((const float4*)(g_diag + b * NN))[i];
    __syncthreads();

    const int warp = threadIdx.x >> 5;
    const int lane = threadIdx.x & 31;
    const int i = blockIdx.x * 8 + warp;
    const float vi = v[i];

    int cnt = 0;
#pragma unroll 4
    for (int j4 = lane; j4 < NN / 4; j4 += 32) {
        float4 w = ((const float4*)v)[j4];
        int j = j4 * 4;
        cnt += (w.x > vi) || ((w.x == vi) && (j + 0 < i));
        cnt += (w.y > vi) || ((w.y == vi) && (j + 1 < i));
        cnt += (w.z > vi) || ((w.z == vi) && (j + 2 < i));
        cnt += (w.w > vi) || ((w.w == vi) && (j + 3 < i));
    }
#pragma unroll
    for (int o = 16; o > 0; o >>= 1) cnt += __shfl_xor_sync(0xffffffffu, cnt, o);

    if (lane == 0) g_sel[b * NN + i] = (cnt < KK) ? 1 : 0;
}

// ============================================================
// Kernel 3b: compaction via block scan
// ============================================================
__global__ __launch_bounds__(1024) void topk_compact_kernel()
{
    const int b = blockIdx.x;
    const int t = threadIdx.x;
    __shared__ int wsum[32];

    const int f0 = g_sel[b * NN + 2 * t];
    const int f1 = g_sel[b * NN + 2 * t + 1];
    const int mysum = f0 + f1;

    int inc = mysum;
#pragma unroll
    for (int o = 1; o < 32; o <<= 1) {
        int u = __shfl_up_sync(0xffffffffu, inc, o);
        if ((t & 31) >= o) inc += u;
    }
    if ((t & 31) == 31) wsum[t >> 5] = inc;
    __syncthreads();
    if (t < 32) {
        int wv = wsum[t];
#pragma unroll
        for (int o = 1; o < 32; o <<= 1) {
            int u = __shfl_up_sync(0xffffffffu, wv, o);
            if (t >= o) wv += u;
        }
        wsum[t] = wv;
    }
    __syncthreads();

    int excl = inc - mysum + ((t >> 5) ? wsum[(t >> 5) - 1] : 0);
    if (f0 && excl < KK)      g_topidx[b * KK + excl] = 2 * t;
    if (f1 && excl + f0 < KK) g_topidx[b * KK + excl + f0] = 2 * t + 1;
}

// ============================================================
// Kernel 4: rel top-R + soi triples; fully parallel scatter
// ============================================================
__global__ __launch_bounds__(128) void rel_kernel(
    const float* __restrict__ scores, float* __restrict__ soi_out)
{
    const int b  = blockIdx.y;
    const int tI = blockIdx.x;
    __shared__ float r[KK];
    __shared__ unsigned char sel[KK];

    const int ti = g_topidx[b * KK + tI];
    const int t  = threadIdx.x;

    if (t < KK) {
        int tj = g_topidx[b * KK + t];
        float val = scores[((size_t)b * NN + ti) * NN + tj];
        r[t] = (t == tI) ? BIGV : val;
    }
    __syncthreads();

    if (t < KK) {
        float vi = r[t];
        int cnt = 0;
#pragma unroll 4
        for (int j = 0; j < KK; j++) {
            float vj = r[j];
            cnt += (vj > vi) || ((vj == vi) && (j < t));
        }
        sel[t] = (cnt < RR) ? 1 : 0;
    }
    __syncthreads();

    if (t < KK && sel[t]) {
        int pos = 0;
#pragma unroll 4
        for (int j = 0; j < KK; j++) pos += (j < t) ? sel[j] : 0;
        if (pos < RR) {
            int obj = g_topidx[b * KK + t];
            int p = (b * KK + tI) * RR + pos;
            g_pairs[2 * p]     = ti;
            g_pairs[2 * p + 1] = obj;
            size_t so = (size_t)p * 3;
            soi_out[so + 0] = (float)b;
            soi_out[so + 1] = (float)ti;
            soi_out[so + 2] = (float)obj;
        }
    }
}

// ============================================================
// Kernel 5: re = LayerNorm(q[b,subj] + q[b,obj])
// ============================================================
__global__ __launch_bounds__(256) void re_kernel(
    const float* __restrict__ q, float* __restrict__ re_out)
{
    const int warp = threadIdx.x >> 5;
    const int lane = threadIdx.x & 31;
    const int p = blockIdx.x * 8 + warp;
    if (p >= BB * KK * RR) return;

    const int b = p / (KK * RR);
    const int subj = g_pairs[2 * p];
    const int obj  = g_pairs[2 * p + 1];
    const float4* qs = (const float4*)(q + ((size_t)b * NN + subj) * DD);
    const float4* qo = (const float4*)(q + ((size_t)b * NN + obj)  * DD);

    float x[8];
    float s = 0.0f, s2 = 0.0f;
#pragma unroll
    for (int c = 0; c < 2; c++) {
        float4 a = qs[lane + 32 * c];
        float4 o = qo[lane + 32 * c];
        x[4 * c + 0] = a.x + o.x; x[4 * c + 1] = a.y + o.y;
        x[4 * c + 2] = a.z + o.z; x[4 * c + 3] = a.w + o.w;
    }
#pragma unroll
    for (int e = 0; e < 8; e++) { s += x[e]; s2 += x[e] * x[e]; }
#pragma unroll
    for (int o = 16; o > 0; o >>= 1) {
        s  += __shfl_xor_sync(0xffffffffu, s,  o);
        s2 += __shfl_xor_sync(0xffffffffu, s2, o);
    }
    const float mu  = s * (1.0f / DD);
    const float var = s2 * (1.0f / DD) - mu * mu;
    const float inv = rsqrtf(var + LN_EPS);

    float4* dst = (float4*)(re_out + (size_t)p * DD);
#pragma unroll
    for (int c = 0; c < 2; c++) {
        float4 r;
        r.x = (x[4 * c + 0] - mu) * inv;
        r.y = (x[4 * c + 1] - mu) * inv;
        r.z = (x[4 * c + 2] - mu) * inv;
        r.w = (x[4 * c + 3] - mu) * inv;
        dst[lane + 32 * c] = r;
    }
}

// ============================================================
extern "C" void kernel_launch(void* const* d_in, const int* in_sizes, int n_in,
                              void* d_out, int out_size)
{
    const float* q = (const float*)d_in[0];
    const float* k = (const float*)d_in[1];

    float* scores = (float*)d_out;
    float* soi    = scores + (size_t)BB * NN * NN;
    float* re     = soi + (size_t)BB * KK * RR * 3;

    void *qs_ptr = nullptr, *ks_ptr = nullptr;
    cudaGetSymbolAddress(&qs_ptr, g_qsb);
    cudaGetSymbolAddress(&ks_ptr, g_ksb);

    cudaFuncSetAttribute(gemm_bf16k, cudaFuncAttributeMaxDynamicSharedMemorySize, SMEM_BYTES);

    split3b_kernel<<<dim3(BB * NN * DD / 8 / 256, 2), 256>>>(q, k);
    gemm_bf16k<<<dim3(NN / BN, NN / BM, BB), 256, SMEM_BYTES>>>(
        (const __nv_bfloat16*)qs_ptr, (const __nv_bfloat16*)ks_ptr, scores);
    softmax_kernel<<<BB * NN, 128>>>(scores);
    topk_count_kernel<<<dim3(NN / 8, BB), 256>>>();
    topk_compact_kernel<<<BB, 1024>>>();
    rel_kernel<<<dim3(KK, BB), 128>>>(scores, soi);
    re_kernel<<<(BB * KK * RR + 7) / 8, 256>>>(q, re);
}

// round 10
// speedup vs baseline: 1.0239x; 1.0239x over previous
#include <cuda_runtime.h>
#include <cuda_bf16.h>
#include <cstdint>

#define BB 8
#define NN 2048
#define DD 256
#define K3 768            // 3-term split K' = 3*DD (bf16)
#define KK 100
#define RR 5
#define BIGV 1000000000.0f
#define LN_EPS 1e-5f

// GEMM tiling
#define BM 128
#define BN 128
#define BKE 64                         // bf16 elems per stage (128 B/row)
#define PADB 72                        // padded row stride in bf16 elems
#define STAGE_H (2 * BM * PADB)        // halves per stage (A+B) = 18432
#define NSTG 3
#define SMEM_BYTES (NSTG * STAGE_H * 2)   // 110592

// ---- scratch (device globals; no allocations allowed) ----
__device__ __align__(128) __nv_bfloat16 g_qsb[(size_t)BB * NN * K3];
__device__ __align__(128) __nv_bfloat16 g_ksb[(size_t)BB * NN * K3];
__device__ float g_diag[BB * NN];
__device__ int   g_sel[BB * NN];
__device__ int   g_topidx[BB * KK];
__device__ int   g_pairs[BB * KK * RR * 2];

// ============================================================
// helpers
// ============================================================
__device__ __forceinline__ void ldsm4(unsigned& r0, unsigned& r1, unsigned& r2, unsigned& r3,
                                      unsigned addr) {
    asm volatile("ldmatrix.sync.aligned.m8n8.x4.shared.b16 {%0,%1,%2,%3}, [%4];"
                 : "=r"(r0), "=r"(r1), "=r"(r2), "=r"(r3) : "r"(addr));
}
__device__ __forceinline__ void mma_bf16(float* d, const unsigned* a, const unsigned* b) {
    asm volatile("mma.sync.aligned.m16n8k16.row.col.f32.bf16.bf16.f32 "
                 "{%0,%1,%2,%3},{%4,%5,%6,%7},{%8,%9},{%0,%1,%2,%3};"
                 : "+f"(d[0]), "+f"(d[1]), "+f"(d[2]), "+f"(d[3])
                 : "r"(a[0]), "r"(a[1]), "r"(a[2]), "r"(a[3]), "r"(b[0]), "r"(b[1]));
}
__device__ __forceinline__ void cpa16(void* smem_dst, const void* gsrc) {
    unsigned d = (unsigned)__cvta_generic_to_shared(smem_dst);
    asm volatile("cp.async.cg.shared.global [%0], [%1], 16;" :: "r"(d), "l"(gsrc));
}

// ============================================================
// Kernel 0: bf16 3-term split.  q -> [qh,qh,ql] ; k -> [kh,kl,kh]
// ============================================================
__global__ __launch_bounds__(256) void split3b_kernel(
    const float* __restrict__ q, const float* __restrict__ k)
{
    const bool isK = blockIdx.y != 0;
    const float4* src = (const float4*)(isK ? k : q);
    __nv_bfloat16* dst = isK ? g_ksb : g_qsb;
    size_t i = (size_t)blockIdx.x * 256 + threadIdx.x;

    float4 v0 = src[2 * i];
    float4 v1 = src[2 * i + 1];
    float xs[8] = {v0.x, v0.y, v0.z, v0.w, v1.x, v1.y, v1.z, v1.w};

    __align__(16) __nv_bfloat16 out[24];
#pragma unroll
    for (int e = 0; e < 8; e++) {
        __nv_bfloat16 h = __float2bfloat16(xs[e]);
        __nv_bfloat16 l = __float2bfloat16(xs[e] - __bfloat162float(h));
        if (!isK) { out[3 * e] = h; out[3 * e + 1] = h; out[3 * e + 2] = l; }
        else      { out[3 * e] = h; out[3 * e + 1] = l; out[3 * e + 2] = h; }
    }
    uint4* o = (uint4*)(dst + 24 * i);
    o[0] = ((uint4*)out)[0];
    o[1] = ((uint4*)out)[1];
    o[2] = ((uint4*)out)[2];
}

// ============================================================
// Kernel 1: bf16 mma.sync m16n8k16 GEMM over K'=768
// 3-stage cp.async pipeline, ONE __syncthreads per iteration
// ============================================================
__global__ __launch_bounds__(256, 2) void gemm_bf16k(
    const __nv_bfloat16* __restrict__ A0, const __nv_bfloat16* __restrict__ B0,
    float* __restrict__ out)
{
    extern __shared__ __nv_bfloat16 sm[];
    const int b = blockIdx.z;
    const int row0 = blockIdx.y * BM;
    const int col0 = blockIdx.x * BN;
    const __nv_bfloat16* A  = A0 + (size_t)b * NN * K3;
    const __nv_bfloat16* Bm = B0 + (size_t)b * NN * K3;
    float* C = out + (size_t)b * NN * NN;

    const int tid = threadIdx.x;
    const int warp = tid >> 5, lane = tid & 31;
    const int wm = (warp >> 2) * 64;
    const int wn = (warp & 3) * 32;

    float acc[4][4][4];
#pragma unroll
    for (int mf = 0; mf < 4; mf++)
#pragma unroll
        for (int nf = 0; nf < 4; nf++)
#pragma unroll
            for (int e = 0; e < 4; e++) acc[mf][nf][e] = 0.0f;

#define LOAD_STAGE(s, kt)                                                      \
    do {                                                                       \
        __nv_bfloat16* As_ = sm + (s) * STAGE_H;                               \
        __nv_bfloat16* Bs_ = As_ + BM * PADB;                                  \
        _Pragma("unroll")                                                      \
        for (int l = 0; l < 4; l++) {                                          \
            int idx = tid + l * 256;                                           \
            int row = idx >> 3;                                                \
            int ce  = (idx & 7) * 8;                                           \
            cpa16(&As_[row * PADB + ce], &A [(size_t)(row0 + row) * K3 + (kt) + ce]); \
            cpa16(&Bs_[row * PADB + ce], &Bm[(size_t)(col0 + row) * K3 + (kt) + ce]); \
        }                                                                      \
        asm volatile("cp.async.commit_group;");                                \
    } while (0)

    LOAD_STAGE(0, 0);
    LOAD_STAGE(1, BKE);

    const int NT = K3 / BKE;   // 12
    int cur = 0, nxt = 2;      // buffer holding tile t; buffer to fill with t+2
    for (int t = 0; t < NT; t++) {
        if (t < NT - 1) { asm volatile("cp.async.wait_group 1;"); }
        else            { asm volatile("cp.async.wait_group 0;"); }
        __syncthreads();                        // single barrier per iter

        if (t + 2 < NT) {
            LOAD_STAGE(nxt, (t + 2) * BKE);     // safe: last readers of 'nxt'
        }                                       // finished before the sync

        const __nv_bfloat16* As_ = sm + cur * STAGE_H;
        const __nv_bfloat16* Bs_ = As_ + BM * PADB;

#pragma unroll
        for (int kk = 0; kk < 4; kk++) {
            const int kb = kk * 16;

            unsigned a[4][4];
#pragma unroll
            for (int mf = 0; mf < 4; mf++) {
                int arow = wm + mf * 16 + (lane & 15);
                int acol = kb + ((lane >> 4) << 3);
                unsigned addr = (unsigned)__cvta_generic_to_shared(&As_[arow * PADB + acol]);
                ldsm4(a[mf][0], a[mf][1], a[mf][2], a[mf][3], addr);
            }
            unsigned bf[4][2];
#pragma unroll
            for (int half = 0; half < 2; half++) {
                int brow = wn + half * 16 + (lane & 7) + ((lane >> 4) << 3);
                int bcol = kb + (((lane >> 3) & 1) << 3);
                unsigned addr = (unsigned)__cvta_generic_to_shared(&Bs_[brow * PADB + bcol]);
                ldsm4(bf[half * 2][0], bf[half * 2][1],
                      bf[half * 2 + 1][0], bf[half * 2 + 1][1], addr);
            }
#pragma unroll
            for (int mf = 0; mf < 4; mf++)
#pragma unroll
                for (int nf = 0; nf < 4; nf++)
                    mma_bf16(acc[mf][nf], a[mf], bf[nf]);
        }

        cur = (cur == 2) ? 0 : cur + 1;
        nxt = (nxt == 2) ? 0 : nxt + 1;
    }
#undef LOAD_STAGE

#pragma unroll
    for (int mf = 0; mf < 4; mf++)
#pragma unroll
        for (int nf = 0; nf < 4; nf++) {
            int r0 = row0 + wm + mf * 16 + (lane >> 2);
            int c0 = col0 + wn + nf * 8 + (lane & 3) * 2;
            *(float2*)&C[(size_t)r0 * NN + c0] =
                make_float2(acc[mf][nf][0], acc[mf][nf][1]);
            *(float2*)&C[(size_t)(r0 + 8) * NN + c0] =
                make_float2(acc[mf][nf][2], acc[mf][nf][3]);
        }
}

// ============================================================
// Kernel 2: in-place row softmax; extract diag (R8 layout:
// 256 threads/row, two float4 per thread)
// ============================================================
__global__ __launch_bounds__(256) void softmax_kernel(float* __restrict__ scores)
{
    const int rowg = blockIdx.x;
    const int i    = rowg & (NN - 1);
    float* row = scores + (size_t)rowg * NN;
    const int t = threadIdx.x;

    float4 v0 = ((float4*)row)[t];
    float4 v1 = ((float4*)row)[t + 256];

    float m = fmaxf(fmaxf(fmaxf(v0.x, v0.y), fmaxf(v0.z, v0.w)),
                    fmaxf(fmaxf(v1.x, v1.y), fmaxf(v1.z, v1.w)));

    __shared__ float red[8];
#pragma unroll
    for (int o = 16; o > 0; o >>= 1) m = fmaxf(m, __shfl_xor_sync(0xffffffffu, m, o));
    if ((t & 31) == 0) red[t >> 5] = m;
    __syncthreads();
    float bm = red[0];
#pragma unroll
    for (int w = 1; w < 8; w++) bm = fmaxf(bm, red[w]);
    __syncthreads();

    v0.x = __expf(v0.x - bm); v0.y = __expf(v0.y - bm);
    v0.z = __expf(v0.z - bm); v0.w = __expf(v0.w - bm);
    v1.x = __expf(v1.x - bm); v1.y = __expf(v1.y - bm);
    v1.z = __expf(v1.z - bm); v1.w = __expf(v1.w - bm);

    float s = v0.x + v0.y + v0.z + v0.w + v1.x + v1.y + v1.z + v1.w;
#pragma unroll
    for (int o = 16; o > 0; o >>= 1) s += __shfl_xor_sync(0xffffffffu, s, o);
    if ((t & 31) == 0) red[t >> 5] = s;
    __syncthreads();
    float bs = 0.0f;
#pragma unroll
    for (int w = 0; w < 8; w++) bs += red[w];

    const float inv = 1.0f / bs;
    v0.x *= inv; v0.y *= inv; v0.z *= inv; v0.w *= inv;
    v1.x *= inv; v1.y *= inv; v1.z *= inv; v1.w *= inv;

    ((float4*)row)[t]       = v0;
    ((float4*)row)[t + 256] = v1;

    int c0 = i >> 2, cc = i & 3;
    if (c0 == t) {
        float d = (cc == 0) ? v0.x : (cc == 1) ? v0.y : (cc == 2) ? v0.z : v0.w;
        g_diag[rowg] = d;
    } else if (c0 == t + 256) {
        float d = (cc == 0) ? v1.x : (cc == 1) ? v1.y : (cc == 2) ? v1.z : v1.w;
        g_diag[rowg] = d;
    }
}

// ============================================================
// Kernel 3a: rank counting — one WARP per element
// ============================================================
__global__ __launch_bounds__(256) void topk_count_kernel()
{
    const int b = blockIdx.y;
    __shared__ __align__(16) float v[NN];

    for (int i = threadIdx.x; i < NN / 4; i += 256)
        ((float4*)v)[i] = ((const float4*)(g_diag + b * NN))[i];
    __syncthreads();

    const int warp = threadIdx.x >> 5;
    const int lane = threadIdx.x & 31;
    const int i = blockIdx.x * 8 + warp;
    const float vi = v[i];

    int cnt = 0;
#pragma unroll 4
    for (int j4 = lane; j4 < NN / 4; j4 += 32) {
        float4 w = ((const float4*)v)[j4];
        int j = j4 * 4;
        cnt += (w.x > vi) || ((w.x == vi) && (j + 0 < i));
        cnt += (w.y > vi) || ((w.y == vi) && (j + 1 < i));
        cnt += (w.z > vi) || ((w.z == vi) && (j + 2 < i));
        cnt += (w.w > vi) || ((w.w == vi) && (j + 3 < i));
    }
#pragma unroll
    for (int o = 16; o > 0; o >>= 1) cnt += __shfl_xor_sync(0xffffffffu, cnt, o);

    if (lane == 0) g_sel[b * NN + i] = (cnt < KK) ? 1 : 0;
}

// ============================================================
// Kernel 3b: compaction via block scan
// ============================================================
__global__ __launch_bounds__(1024) void topk_compact_kernel()
{
    const int b = blockIdx.x;
    const int t = threadIdx.x;
    __shared__ int wsum[32];

    const int f0 = g_sel[b * NN + 2 * t];
    const int f1 = g_sel[b * NN + 2 * t + 1];
    const int mysum = f0 + f1;

    int inc = mysum;
#pragma unroll
    for (int o = 1; o < 32; o <<= 1) {
        int u = __shfl_up_sync(0xffffffffu, inc, o);
        if ((t & 31) >= o) inc += u;
    }
    if ((t & 31) == 31) wsum[t >> 5] = inc;
    __syncthreads();
    if (t < 32) {
        int wv = wsum[t];
#pragma unroll
        for (int o = 1; o < 32; o <<= 1) {
            int u = __shfl_up_sync(0xffffffffu, wv, o);
            if (t >= o) wv += u;
        }
        wsum[t] = wv;
    }
    __syncthreads();

    int excl = inc - mysum + ((t >> 5) ? wsum[(t >> 5) - 1] : 0);
    if (f0 && excl < KK)      g_topidx[b * KK + excl] = 2 * t;
    if (f1 && excl + f0 < KK) g_topidx[b * KK + excl + f0] = 2 * t + 1;
}

// ============================================================
// Kernel 4: rel top-R + soi triples; fully parallel scatter
// ============================================================
__global__ __launch_bounds__(128) void rel_kernel(
    const float* __restrict__ scores, float* __restrict__ soi_out)
{
    const int b  = blockIdx.y;
    const int tI = blockIdx.x;
    __shared__ float r[KK];
    __shared__ unsigned char sel[KK];

    const int ti = g_topidx[b * KK + tI];
    const int t  = threadIdx.x;

    if (t < KK) {
        int tj = g_topidx[b * KK + t];
        float val = scores[((size_t)b * NN + ti) * NN + tj];
        r[t] = (t == tI) ? BIGV : val;
    }
    __syncthreads();

    if (t < KK) {
        float vi = r[t];
        int cnt = 0;
#pragma unroll 4
        for (int j = 0; j < KK; j++) {
            float vj = r[j];
            cnt += (vj > vi) || ((vj == vi) && (j < t));
        }
        sel[t] = (cnt < RR) ? 1 : 0;
    }
    __syncthreads();

    if (t < KK && sel[t]) {
        int pos = 0;
#pragma unroll 4
        for (int j = 0; j < KK; j++) pos += (j < t) ? sel[j] : 0;
        if (pos < RR) {
            int obj = g_topidx[b * KK + t];
            int p = (b * KK + tI) * RR + pos;
            g_pairs[2 * p]     = ti;
            g_pairs[2 * p + 1] = obj;
            size_t so = (size_t)p * 3;
            soi_out[so + 0] = (float)b;
            soi_out[so + 1] = (float)ti;
            soi_out[so + 2] = (float)obj;
        }
    }
}

// ============================================================
// Kernel 5: re = LayerNorm(q[b,subj] + q[b,obj])
// ============================================================
__global__ __launch_bounds__(256) void re_kernel(
    const float* __restrict__ q, float* __restrict__ re_out)
{
    const int warp = threadIdx.x >> 5;
    const int lane = threadIdx.x & 31;
    const int p = blockIdx.x * 8 + warp;
    if (p >= BB * KK * RR) return;

    const int b = p / (KK * RR);
    const int subj = g_pairs[2 * p];
    const int obj  = g_pairs[2 * p + 1];
    const float4* qs = (const float4*)(q + ((size_t)b * NN + subj) * DD);
    const float4* qo = (const float4*)(q + ((size_t)b * NN + obj)  * DD);

    float x[8];
    float s = 0.0f, s2 = 0.0f;
#pragma unroll
    for (int c = 0; c < 2; c++) {
        float4 a = qs[lane + 32 * c];
        float4 o = qo[lane + 32 * c];
        x[4 * c + 0] = a.x + o.x; x[4 * c + 1] = a.y + o.y;
        x[4 * c + 2] = a.z + o.z; x[4 * c + 3] = a.w + o.w;
    }
#pragma unroll
    for (int e = 0; e < 8; e++) { s += x[e]; s2 += x[e] * x[e]; }
#pragma unroll
    for (int o = 16; o > 0; o >>= 1) {
        s  += __shfl_xor_sync(0xffffffffu, s,  o);
        s2 += __shfl_xor_sync(0xffffffffu, s2, o);
    }
    const float mu  = s * (1.0f / DD);
    const float var = s2 * (1.0f / DD) - mu * mu;
    const float inv = rsqrtf(var + LN_EPS);

    float4* dst = (float4*)(re_out + (size_t)p * DD);
#pragma unroll
    for (int c = 0; c < 2; c++) {
        float4 r;
        r.x = (x[4 * c + 0] - mu) * inv;
        r.y = (x[4 * c + 1] - mu) * inv;
        r.z = (x[4 * c + 2] - mu) * inv;
        r.w = (x[4 * c + 3] - mu) * inv;
        dst[lane + 32 * c] = r;
    }
}

// ============================================================
extern "C" void kernel_launch(void* const* d_in, const int* in_sizes, int n_in,
                              void* d_out, int out_size)
{
    const float* q = (const float*)d_in[0];
    const float* k = (const float*)d_in[1];

    float* scores = (float*)d_out;
    float* soi    = scores + (size_t)BB * NN * NN;
    float* re     = soi + (size_t)BB * KK * RR * 3;

    void *qs_ptr = nullptr, *ks_ptr = nullptr;
    cudaGetSymbolAddress(&qs_ptr, g_qsb);
    cudaGetSymbolAddress(&ks_ptr, g_ksb);

    cudaFuncSetAttribute(gemm_bf16k, cudaFuncAttributeMaxDynamicSharedMemorySize, SMEM_BYTES);

    split3b_kernel<<<dim3(BB * NN * DD / 8 / 256, 2), 256>>>(q, k);
    gemm_bf16k<<<dim3(NN / BN, NN / BM, BB), 256, SMEM_BYTES>>>(
        (const __nv_bfloat16*)qs_ptr, (const __nv_bfloat16*)ks_ptr, scores);
    softmax_kernel<<<BB * NN, 256>>>(scores);
    topk_count_kernel<<<dim3(NN / 8, BB), 256>>>();
    topk_compact_kernel<<<BB, 1024>>>();
    rel_kernel<<<dim3(KK, BB), 128>>>(scores, soi);
    re_kernel<<<(BB * KK * RR + 7) / 8, 256>>>(q, re);
}

// round 11
// speedup vs baseline: 1.0256x; 1.0017x over previous
#include <cuda_runtime.h>
#include <cuda_bf16.h>
#include <cstdint>

#define BB 8
#define NN 2048
#define DD 256
#define K3 768            // 3-term split K' = 3*DD (bf16)
#define KK 100
#define RR 5
#define BIGV 1000000000.0f
#define LN_EPS 1e-5f

// GEMM tiling
#define BM 128
#define BN 128
#define BKE 64                         // bf16 elems per stage (128 B/row)
#define PADB 72                        // padded row stride in bf16 elems
#define STAGE_H (2 * BM * PADB)        // halves per stage (A+B) = 18432
#define NSTG 3
#define SMEM_BYTES (NSTG * STAGE_H * 2)   // 110592

// ---- scratch (device globals; no allocations allowed) ----
__device__ __align__(128) __nv_bfloat16 g_qsb[(size_t)BB * NN * K3];
__device__ __align__(128) __nv_bfloat16 g_ksb[(size_t)BB * NN * K3];
__device__ float g_diag[BB * NN];
__device__ int   g_sel[BB * NN];
__device__ int   g_topidx[BB * KK];
__device__ int   g_pairs[BB * KK * RR * 2];

// ============================================================
// helpers
// ============================================================
__device__ __forceinline__ void ldsm4(unsigned& r0, unsigned& r1, unsigned& r2, unsigned& r3,
                                      unsigned addr) {
    asm volatile("ldmatrix.sync.aligned.m8n8.x4.shared.b16 {%0,%1,%2,%3}, [%4];"
                 : "=r"(r0), "=r"(r1), "=r"(r2), "=r"(r3) : "r"(addr));
}
__device__ __forceinline__ void mma_bf16(float* d, const unsigned* a, const unsigned* b) {
    asm volatile("mma.sync.aligned.m16n8k16.row.col.f32.bf16.bf16.f32 "
                 "{%0,%1,%2,%3},{%4,%5,%6,%7},{%8,%9},{%0,%1,%2,%3};"
                 : "+f"(d[0]), "+f"(d[1]), "+f"(d[2]), "+f"(d[3])
                 : "r"(a[0]), "r"(a[1]), "r"(a[2]), "r"(a[3]), "r"(b[0]), "r"(b[1]));
}
__device__ __forceinline__ void cpa16(void* smem_dst, const void* gsrc) {
    unsigned d = (unsigned)__cvta_generic_to_shared(smem_dst);
    asm volatile("cp.async.cg.shared.global [%0], [%1], 16;" :: "r"(d), "l"(gsrc));
}

// ============================================================
// Kernel 0: bf16 3-term split.  q -> [qh,qh,ql] ; k -> [kh,kl,kh]
// ============================================================
__global__ __launch_bounds__(256) void split3b_kernel(
    const float* __restrict__ q, const float* __restrict__ k)
{
    const bool isK = blockIdx.y != 0;
    const float4* src = (const float4*)(isK ? k : q);
    __nv_bfloat16* dst = isK ? g_ksb : g_qsb;
    size_t i = (size_t)blockIdx.x * 256 + threadIdx.x;

    float4 v0 = src[2 * i];
    float4 v1 = src[2 * i + 1];
    float xs[8] = {v0.x, v0.y, v0.z, v0.w, v1.x, v1.y, v1.z, v1.w};

    __align__(16) __nv_bfloat16 out[24];
#pragma unroll
    for (int e = 0; e < 8; e++) {
        __nv_bfloat16 h = __float2bfloat16(xs[e]);
        __nv_bfloat16 l = __float2bfloat16(xs[e] - __bfloat162float(h));
        if (!isK) { out[3 * e] = h; out[3 * e + 1] = h; out[3 * e + 2] = l; }
        else      { out[3 * e] = h; out[3 * e + 1] = l; out[3 * e + 2] = h; }
    }
    uint4* o = (uint4*)(dst + 24 * i);
    o[0] = ((uint4*)out)[0];
    o[1] = ((uint4*)out)[1];
    o[2] = ((uint4*)out)[2];
}

// ============================================================
// Kernel 1: bf16 mma.sync m16n8k16 GEMM over K'=768
// 3-stage cp.async pipeline, ONE __syncthreads per iteration
// ============================================================
__global__ __launch_bounds__(256, 2) void gemm_bf16k(
    const __nv_bfloat16* __restrict__ A0, const __nv_bfloat16* __restrict__ B0,
    float* __restrict__ out)
{
    extern __shared__ __nv_bfloat16 sm[];
    const int b = blockIdx.z;
    const int row0 = blockIdx.y * BM;
    const int col0 = blockIdx.x * BN;
    const __nv_bfloat16* A  = A0 + (size_t)b * NN * K3;
    const __nv_bfloat16* Bm = B0 + (size_t)b * NN * K3;
    float* C = out + (size_t)b * NN * NN;

    const int tid = threadIdx.x;
    const int warp = tid >> 5, lane = tid & 31;
    const int wm = (warp >> 2) * 64;
    const int wn = (warp & 3) * 32;

    float acc[4][4][4];
#pragma unroll
    for (int mf = 0; mf < 4; mf++)
#pragma unroll
        for (int nf = 0; nf < 4; nf++)
#pragma unroll
            for (int e = 0; e < 4; e++) acc[mf][nf][e] = 0.0f;

#define LOAD_STAGE(s, kt)                                                      \
    do {                                                                       \
        __nv_bfloat16* As_ = sm + (s) * STAGE_H;                               \
        __nv_bfloat16* Bs_ = As_ + BM * PADB;                                  \
        _Pragma("unroll")                                                      \
        for (int l = 0; l < 4; l++) {                                          \
            int idx = tid + l * 256;                                           \
            int row = idx >> 3;                                                \
            int ce  = (idx & 7) * 8;                                           \
            cpa16(&As_[row * PADB + ce], &A [(size_t)(row0 + row) * K3 + (kt) + ce]); \
            cpa16(&Bs_[row * PADB + ce], &Bm[(size_t)(col0 + row) * K3 + (kt) + ce]); \
        }                                                                      \
        asm volatile("cp.async.commit_group;");                                \
    } while (0)

    LOAD_STAGE(0, 0);
    LOAD_STAGE(1, BKE);

    const int NT = K3 / BKE;   // 12
    int cur = 0, nxt = 2;
    for (int t = 0; t < NT; t++) {
        if (t < NT - 1) { asm volatile("cp.async.wait_group 1;"); }
        else            { asm volatile("cp.async.wait_group 0;"); }
        __syncthreads();

        if (t + 2 < NT) {
            LOAD_STAGE(nxt, (t + 2) * BKE);
        }

        const __nv_bfloat16* As_ = sm + cur * STAGE_H;
        const __nv_bfloat16* Bs_ = As_ + BM * PADB;

#pragma unroll
        for (int kk = 0; kk < 4; kk++) {
            const int kb = kk * 16;

            unsigned a[4][4];
#pragma unroll
            for (int mf = 0; mf < 4; mf++) {
                int arow = wm + mf * 16 + (lane & 15);
                int acol = kb + ((lane >> 4) << 3);
                unsigned addr = (unsigned)__cvta_generic_to_shared(&As_[arow * PADB + acol]);
                ldsm4(a[mf][0], a[mf][1], a[mf][2], a[mf][3], addr);
            }
            unsigned bf[4][2];
#pragma unroll
            for (int half = 0; half < 2; half++) {
                int brow = wn + half * 16 + (lane & 7) + ((lane >> 4) << 3);
                int bcol = kb + (((lane >> 3) & 1) << 3);
                unsigned addr = (unsigned)__cvta_generic_to_shared(&Bs_[brow * PADB + bcol]);
                ldsm4(bf[half * 2][0], bf[half * 2][1],
                      bf[half * 2 + 1][0], bf[half * 2 + 1][1], addr);
            }
#pragma unroll
            for (int mf = 0; mf < 4; mf++)
#pragma unroll
                for (int nf = 0; nf < 4; nf++)
                    mma_bf16(acc[mf][nf], a[mf], bf[nf]);
        }

        cur = (cur == 2) ? 0 : cur + 1;
        nxt = (nxt == 2) ? 0 : nxt + 1;
    }
#undef LOAD_STAGE

#pragma unroll
    for (int mf = 0; mf < 4; mf++)
#pragma unroll
        for (int nf = 0; nf < 4; nf++) {
            int r0 = row0 + wm + mf * 16 + (lane >> 2);
            int c0 = col0 + wn + nf * 8 + (lane & 3) * 2;
            *(float2*)&C[(size_t)r0 * NN + c0] =
                make_float2(acc[mf][nf][0], acc[mf][nf][1]);
            *(float2*)&C[(size_t)(r0 + 8) * NN + c0] =
                make_float2(acc[mf][nf][2], acc[mf][nf][3]);
        }
}

// ============================================================
// Kernel 2: in-place row softmax; extract diag.
// TWO rows per block, 256 threads; each thread: 2 float4 per row
// (MLP=4 loads in flight, reductions amortized over 2 rows)
// ============================================================
__global__ __launch_bounds__(256) void softmax_kernel(float* __restrict__ scores)
{
    const int rowg0 = blockIdx.x * 2;        // first of two rows
    const int i0 = rowg0 & (NN - 1);
    const int i1 = (rowg0 + 1) & (NN - 1);
    float* rowA = scores + (size_t)rowg0 * NN;
    float* rowB = rowA + NN;
    const int t = threadIdx.x;

    float4 a0 = ((float4*)rowA)[t];
    float4 a1 = ((float4*)rowA)[t + 256];
    float4 b0 = ((float4*)rowB)[t];
    float4 b1 = ((float4*)rowB)[t + 256];

    float ma = fmaxf(fmaxf(fmaxf(a0.x, a0.y), fmaxf(a0.z, a0.w)),
                     fmaxf(fmaxf(a1.x, a1.y), fmaxf(a1.z, a1.w)));
    float mb = fmaxf(fmaxf(fmaxf(b0.x, b0.y), fmaxf(b0.z, b0.w)),
                     fmaxf(fmaxf(b1.x, b1.y), fmaxf(b1.z, b1.w)));

    __shared__ float redA[8], redB[8];
#pragma unroll
    for (int o = 16; o > 0; o >>= 1) {
        ma = fmaxf(ma, __shfl_xor_sync(0xffffffffu, ma, o));
        mb = fmaxf(mb, __shfl_xor_sync(0xffffffffu, mb, o));
    }
    if ((t & 31) == 0) { redA[t >> 5] = ma; redB[t >> 5] = mb; }
    __syncthreads();
    float bmA = redA[0], bmB = redB[0];
#pragma unroll
    for (int w = 1; w < 8; w++) {
        bmA = fmaxf(bmA, redA[w]);
        bmB = fmaxf(bmB, redB[w]);
    }
    __syncthreads();

    a0.x = __expf(a0.x - bmA); a0.y = __expf(a0.y - bmA);
    a0.z = __expf(a0.z - bmA); a0.w = __expf(a0.w - bmA);
    a1.x = __expf(a1.x - bmA); a1.y = __expf(a1.y - bmA);
    a1.z = __expf(a1.z - bmA); a1.w = __expf(a1.w - bmA);
    b0.x = __expf(b0.x - bmB); b0.y = __expf(b0.y - bmB);
    b0.z = __expf(b0.z - bmB); b0.w = __expf(b0.w - bmB);
    b1.x = __expf(b1.x - bmB); b1.y = __expf(b1.y - bmB);
    b1.z = __expf(b1.z - bmB); b1.w = __expf(b1.w - bmB);

    float sa = a0.x + a0.y + a0.z + a0.w + a1.x + a1.y + a1.z + a1.w;
    float sb = b0.x + b0.y + b0.z + b0.w + b1.x + b1.y + b1.z + b1.w;
#pragma unroll
    for (int o = 16; o > 0; o >>= 1) {
        sa += __shfl_xor_sync(0xffffffffu, sa, o);
        sb += __shfl_xor_sync(0xffffffffu, sb, o);
    }
    if ((t & 31) == 0) { redA[t >> 5] = sa; redB[t >> 5] = sb; }
    __syncthreads();
    float bsA = 0.0f, bsB = 0.0f;
#pragma unroll
    for (int w = 0; w < 8; w++) { bsA += redA[w]; bsB += redB[w]; }

    const float invA = 1.0f / bsA;
    const float invB = 1.0f / bsB;
    a0.x *= invA; a0.y *= invA; a0.z *= invA; a0.w *= invA;
    a1.x *= invA; a1.y *= invA; a1.z *= invA; a1.w *= invA;
    b0.x *= invB; b0.y *= invB; b0.z *= invB; b0.w *= invB;
    b1.x *= invB; b1.y *= invB; b1.z *= invB; b1.w *= invB;

    ((float4*)rowA)[t]       = a0;
    ((float4*)rowA)[t + 256] = a1;
    ((float4*)rowB)[t]       = b0;
    ((float4*)rowB)[t + 256] = b1;

    // diag for row A
    {
        int c0 = i0 >> 2, cc = i0 & 3;
        if (c0 == t) {
            float d = (cc == 0) ? a0.x : (cc == 1) ? a0.y : (cc == 2) ? a0.z : a0.w;
            g_diag[rowg0] = d;
        } else if (c0 == t + 256) {
            float d = (cc == 0) ? a1.x : (cc == 1) ? a1.y : (cc == 2) ? a1.z : a1.w;
            g_diag[rowg0] = d;
        }
    }
    // diag for row B
    {
        int c0 = i1 >> 2, cc = i1 & 3;
        if (c0 == t) {
            float d = (cc == 0) ? b0.x : (cc == 1) ? b0.y : (cc == 2) ? b0.z : b0.w;
            g_diag[rowg0 + 1] = d;
        } else if (c0 == t + 256) {
            float d = (cc == 0) ? b1.x : (cc == 1) ? b1.y : (cc == 2) ? b1.z : b1.w;
            g_diag[rowg0 + 1] = d;
        }
    }
}

// ============================================================
// Kernel 3a: rank counting — one WARP per element
// ============================================================
__global__ __launch_bounds__(256) void topk_count_kernel()
{
    const int b = blockIdx.y;
    __shared__ __align__(16) float v[NN];

    for (int i = threadIdx.x; i < NN / 4; i += 256)
        ((float4*)v)[i] = ((const float4*)(g_diag + b * NN))[i];
    __syncthreads();

    const int warp = threadIdx.x >> 5;
    const int lane = threadIdx.x & 31;
    const int i = blockIdx.x * 8 + warp;
    const float vi = v[i];

    int cnt = 0;
#pragma unroll 4
    for (int j4 = lane; j4 < NN / 4; j4 += 32) {
        float4 w = ((const float4*)v)[j4];
        int j = j4 * 4;
        cnt += (w.x > vi) || ((w.x == vi) && (j + 0 < i));
        cnt += (w.y > vi) || ((w.y == vi) && (j + 1 < i));
        cnt += (w.z > vi) || ((w.z == vi) && (j + 2 < i));
        cnt += (w.w > vi) || ((w.w == vi) && (j + 3 < i));
    }
#pragma unroll
    for (int o = 16; o > 0; o >>= 1) cnt += __shfl_xor_sync(0xffffffffu, cnt, o);

    if (lane == 0) g_sel[b * NN + i] = (cnt < KK) ? 1 : 0;
}

// ============================================================
// Kernel 3b: compaction via block scan
// ============================================================
__global__ __launch_bounds__(1024) void topk_compact_kernel()
{
    const int b = blockIdx.x;
    const int t = threadIdx.x;
    __shared__ int wsum[32];

    const int f0 = g_sel[b * NN + 2 * t];
    const int f1 = g_sel[b * NN + 2 * t + 1];
    const int mysum = f0 + f1;

    int inc = mysum;
#pragma unroll
    for (int o = 1; o < 32; o <<= 1) {
        int u = __shfl_up_sync(0xffffffffu, inc, o);
        if ((t & 31) >= o) inc += u;
    }
    if ((t & 31) == 31) wsum[t >> 5] = inc;
    __syncthreads();
    if (t < 32) {
        int wv = wsum[t];
#pragma unroll
        for (int o = 1; o < 32; o <<= 1) {
            int u = __shfl_up_sync(0xffffffffu, wv, o);
            if (t >= o) wv += u;
        }
        wsum[t] = wv;
    }
    __syncthreads();

    int excl = inc - mysum + ((t >> 5) ? wsum[(t >> 5) - 1] : 0);
    if (f0 && excl < KK)      g_topidx[b * KK + excl] = 2 * t;
    if (f1 && excl + f0 < KK) g_topidx[b * KK + excl + f0] = 2 * t + 1;
}

// ============================================================
// Kernel 4: rel top-R + soi triples; fully parallel scatter
// ============================================================
__global__ __launch_bounds__(128) void rel_kernel(
    const float* __restrict__ scores, float* __restrict__ soi_out)
{
    const int b  = blockIdx.y;
    const int tI = blockIdx.x;
    __shared__ float r[KK];
    __shared__ unsigned char sel[KK];

    const int ti = g_topidx[b * KK + tI];
    const int t  = threadIdx.x;

    if (t < KK) {
        int tj = g_topidx[b * KK + t];
        float val = scores[((size_t)b * NN + ti) * NN + tj];
        r[t] = (t == tI) ? BIGV : val;
    }
    __syncthreads();

    if (t < KK) {
        float vi = r[t];
        int cnt = 0;
#pragma unroll 4
        for (int j = 0; j < KK; j++) {
            float vj = r[j];
            cnt += (vj > vi) || ((vj == vi) && (j < t));
        }
        sel[t] = (cnt < RR) ? 1 : 0;
    }
    __syncthreads();

    if (t < KK && sel[t]) {
        int pos = 0;
#pragma unroll 4
        for (int j = 0; j < KK; j++) pos += (j < t) ? sel[j] : 0;
        if (pos < RR) {
            int obj = g_topidx[b * KK + t];
            int p = (b * KK + tI) * RR + pos;
            g_pairs[2 * p]     = ti;
            g_pairs[2 * p + 1] = obj;
            size_t so = (size_t)p * 3;
            soi_out[so + 0] = (float)b;
            soi_out[so + 1] = (float)ti;
            soi_out[so + 2] = (float)obj;
        }
    }
}

// ============================================================
// Kernel 5: re = LayerNorm(q[b,subj] + q[b,obj])
// ============================================================
__global__ __launch_bounds__(256) void re_kernel(
    const float* __restrict__ q, float* __restrict__ re_out)
{
    const int warp = threadIdx.x >> 5;
    const int lane = threadIdx.x & 31;
    const int p = blockIdx.x * 8 + warp;
    if (p >= BB * KK * RR) return;

    const int b = p / (KK * RR);
    const int subj = g_pairs[2 * p];
    const int obj  = g_pairs[2 * p + 1];
    const float4* qs = (const float4*)(q + ((size_t)b * NN + subj) * DD);
    const float4* qo = (const float4*)(q + ((size_t)b * NN + obj)  * DD);

    float x[8];
    float s = 0.0f, s2 = 0.0f;
#pragma unroll
    for (int c = 0; c < 2; c++) {
        float4 a = qs[lane + 32 * c];
        float4 o = qo[lane + 32 * c];
        x[4 * c + 0] = a.x + o.x; x[4 * c + 1] = a.y + o.y;
        x[4 * c + 2] = a.z + o.z; x[4 * c + 3] = a.w + o.w;
    }
#pragma unroll
    for (int e = 0; e < 8; e++) { s += x[e]; s2 += x[e] * x[e]; }
#pragma unroll
    for (int o = 16; o > 0; o >>= 1) {
        s  += __shfl_xor_sync(0xffffffffu, s,  o);
        s2 += __shfl_xor_sync(0xffffffffu, s2, o);
    }
    const float mu  = s * (1.0f / DD);
    const float var = s2 * (1.0f / DD) - mu * mu;
    const float inv = rsqrtf(var + LN_EPS);

    float4* dst = (float4*)(re_out + (size_t)p * DD);
#pragma unroll
    for (int c = 0; c < 2; c++) {
        float4 r;
        r.x = (x[4 * c + 0] - mu) * inv;
        r.y = (x[4 * c + 1] - mu) * inv;
        r.z = (x[4 * c + 2] - mu) * inv;
        r.w = (x[4 * c + 3] - mu) * inv;
        dst[lane + 32 * c] = r;
    }
}

// ============================================================
extern "C" void kernel_launch(void* const* d_in, const int* in_sizes, int n_in,
                              void* d_out, int out_size)
{
    const float* q = (const float*)d_in[0];
    const float* k = (const float*)d_in[1];

    float* scores = (float*)d_out;
    float* soi    = scores + (size_t)BB * NN * NN;
    float* re     = soi + (size_t)BB * KK * RR * 3;

    void *qs_ptr = nullptr, *ks_ptr = nullptr;
    cudaGetSymbolAddress(&qs_ptr, g_qsb);
    cudaGetSymbolAddress(&ks_ptr, g_ksb);

    cudaFuncSetAttribute(gemm_bf16k, cudaFuncAttributeMaxDynamicSharedMemorySize, SMEM_BYTES);

    split3b_kernel<<<dim3(BB * NN * DD / 8 / 256, 2), 256>>>(q, k);
    gemm_bf16k<<<dim3(NN / BN, NN / BM, BB), 256, SMEM_BYTES>>>(
        (const __nv_bfloat16*)qs_ptr, (const __nv_bfloat16*)ks_ptr, scores);
    softmax_kernel<<<BB * NN / 2, 256>>>(scores);
    topk_count_kernel<<<dim3(NN / 8, BB), 256>>>();
    topk_compact_kernel<<<BB, 1024>>>();
    rel_kernel<<<dim3(KK, BB), 128>>>(scores, soi);
    re_kernel<<<(BB * KK * RR + 7) / 8, 256>>>(q, re);
}